// round 8
// baseline (speedup 1.0000x reference)
#include <cuda_runtime.h>

#define D_DIM 2048
#define E_DIM 64
#define BR 256
#define DK 32
#define NT 256
#define NTILE (D_DIM / DK)   // 64

__device__ float g_partial[512 * E_DIM];
__device__ unsigned int g_counter = 0;

static __device__ __forceinline__ unsigned long long pack2(float lo, float hi) {
    unsigned long long r;
    asm("mov.b64 %0, {%1, %2};" : "=l"(r) : "f"(lo), "f"(hi));
    return r;
}
static __device__ __forceinline__ void unpack2(unsigned long long v, float& lo, float& hi) {
    asm("mov.b64 {%0, %1}, %2;" : "=f"(lo), "=f"(hi) : "l"(v));
}
static __device__ __forceinline__ void fma2(unsigned long long& d, unsigned long long a, unsigned long long b) {
    asm("fma.rn.f32x2 %0, %1, %2, %0;" : "+l"(d) : "l"(a), "l"(b));
}

__global__ __launch_bounds__(NT, 1) void router_fused_kernel(
    const float* __restrict__ x, const float* __restrict__ W,
    const float* __restrict__ bias,
    float* __restrict__ mask_out, float* __restrict__ prob_out,
    float* __restrict__ imp, float* __restrict__ ld)
{
    // x transposed: xs[k][row], row column XOR-swizzled by 4*((k>>2)&7).
    // -> transpose STS conflict-free, mainloop LDS.128 conflict-free, 16B aligned.
    __shared__ float xs[DK][BR];            // 32 KB
    // W tile chunk-permuted: chunk c16 -> float offset (c16>>1)*4 + (c16&1)*32,
    // so wa/wb LDS.128 chunks hit 8 distinct bank quads.
    __shared__ float ws[DK][E_DIM];         // 8 KB
    __shared__ float psum[4][E_DIM];
    __shared__ unsigned int s_last;

    const int tid = threadIdx.x;
    const int tx = tid & 7;                 // expert group (8 experts)
    const int ty = tid >> 3;                // 0..31 -> rows ty*8..ty*8+7
    const int row0 = blockIdx.x * BR;
    const float* xb = x + (size_t)row0 * D_DIM;

    // accumulators: 8 rows x 4 f32x2 pairs (8 experts), bias folded in
    unsigned long long acc2[8][4];
    {
        float b0[8];
#pragma unroll
        for (int j = 0; j < 8; j++) b0[j] = bias[tx * 8 + j];
#pragma unroll
        for (int i = 0; i < 8; i++)
#pragma unroll
            for (int j = 0; j < 4; j++)
                acc2[i][j] = pack2(b0[2 * j], b0[2 * j + 1]);
    }

    // software pipeline registers
    float4 xr[8], wr[2];
#pragma unroll
    for (int p = 0; p < 8; p++)
        xr[p] = *reinterpret_cast<const float4*>(xb + (size_t)(ty + p * 32) * D_DIM + tx * 4);
#pragma unroll
    for (int q = 0; q < 2; q++) {
        int id = tid * 2 + q;
        wr[q] = *reinterpret_cast<const float4*>(W + (size_t)(id >> 4) * E_DIM + (id & 15) * 4);
    }

    for (int t = 0; t < NTILE; t++) {
        // commit x transposed with swizzle: phys col = r ^ (4*tx), k = tx*4+j
#pragma unroll
        for (int p = 0; p < 8; p++) {
            int r = ty + p * 32;
            int pc = r ^ (tx * 4);
            xs[tx * 4 + 0][pc] = xr[p].x;
            xs[tx * 4 + 1][pc] = xr[p].y;
            xs[tx * 4 + 2][pc] = xr[p].z;
            xs[tx * 4 + 3][pc] = xr[p].w;
        }
#pragma unroll
        for (int q = 0; q < 2; q++) {
            int id = tid * 2 + q;
            int kk = id >> 4, c16 = id & 15;
            int dst = (c16 >> 1) * 4 + (c16 & 1) * 32;
            *reinterpret_cast<float4*>(&ws[kk][dst]) = wr[q];
        }
        __syncthreads();

        // next tile's global loads (hidden behind compute)
        if (t + 1 < NTILE) {
            const int k0 = (t + 1) * DK;
#pragma unroll
            for (int p = 0; p < 8; p++)
                xr[p] = *reinterpret_cast<const float4*>(xb + (size_t)(ty + p * 32) * D_DIM + k0 + tx * 4);
#pragma unroll
            for (int q = 0; q < 2; q++) {
                int id = tid * 2 + q;
                wr[q] = *reinterpret_cast<const float4*>(W + (size_t)(k0 + (id >> 4)) * E_DIM + (id & 15) * 4);
            }
        }

#pragma unroll
        for (int kk = 0; kk < DK; kk++) {
            ulonglong2 wa = *reinterpret_cast<const ulonglong2*>(&ws[kk][tx * 4]);       // e 8tx..+3
            ulonglong2 wb = *reinterpret_cast<const ulonglong2*>(&ws[kk][32 + tx * 4]);  // e 8tx+4..+7
            const int swz = 4 * ((kk >> 2) & 7);
            float4 xa = *reinterpret_cast<const float4*>(&xs[kk][(ty * 8) ^ swz]);       // rows ty*8..+3
            float4 xb4 = *reinterpret_cast<const float4*>(&xs[kk][(ty * 8 + 4) ^ swz]);  // rows ty*8+4..+7
            const float xv[8] = {xa.x, xa.y, xa.z, xa.w, xb4.x, xb4.y, xb4.z, xb4.w};
#pragma unroll
            for (int i = 0; i < 8; i++) {
                unsigned long long xx = pack2(xv[i], xv[i]);
                fma2(acc2[i][0], xx, wa.x);
                fma2(acc2[i][1], xx, wa.y);
                fma2(acc2[i][2], xx, wb.x);
                fma2(acc2[i][3], xx, wb.y);
            }
        }
        __syncthreads();
    }

    // ---------------- epilogue: softmax + top-3 + outputs ----------------
    float loadacc[8];
#pragma unroll
    for (int j = 0; j < 8; j++) loadacc[j] = 0.f;

#pragma unroll
    for (int i = 0; i < 8; i++) {
        float lg[8];
#pragma unroll
        for (int j = 0; j < 4; j++) unpack2(acc2[i][j], lg[2 * j], lg[2 * j + 1]);

        float m = lg[0];
#pragma unroll
        for (int j = 1; j < 8; j++) m = fmaxf(m, lg[j]);
#pragma unroll
        for (int d = 1; d < 8; d <<= 1) m = fmaxf(m, __shfl_xor_sync(0xffffffffu, m, d));
        float ev[8], ssum = 0.f;
#pragma unroll
        for (int j = 0; j < 8; j++) { ev[j] = __expf(lg[j] - m); ssum += ev[j]; }
#pragma unroll
        for (int d = 1; d < 8; d <<= 1) ssum += __shfl_xor_sync(0xffffffffu, ssum, d);
        float inv = 1.0f / ssum;

        unsigned chosenMask = 0u;
#pragma unroll
        for (int t = 0; t < 3; t++) {
            float bvv = -3.0e38f; int bi = 1 << 20;
#pragma unroll
            for (int j = 0; j < 8; j++) {
                float v = ((chosenMask >> j) & 1u) ? -3.0e38f : lg[j];
                if (v > bvv) { bvv = v; bi = tx * 8 + j; }
            }
#pragma unroll
            for (int d = 1; d < 8; d <<= 1) {
                float ov = __shfl_xor_sync(0xffffffffu, bvv, d);
                int   oi = __shfl_xor_sync(0xffffffffu, bi, d);
                if (ov > bvv || (ov == bvv && oi < bi)) { bvv = ov; bi = oi; }
            }
            if ((bi >> 3) == tx) chosenMask |= 1u << (bi & 7);
        }

        float pr[8], mk[8];
#pragma unroll
        for (int j = 0; j < 8; j++) {
            pr[j] = ev[j] * inv;
            mk[j] = ((chosenMask >> j) & 1u) ? 1.0f : 0.0f;
            loadacc[j] += pr[j];
        }
        size_t base = ((size_t)(row0 + ty * 8 + i)) * E_DIM + tx * 8;
        *reinterpret_cast<float4*>(prob_out + base)     = make_float4(pr[0], pr[1], pr[2], pr[3]);
        *reinterpret_cast<float4*>(prob_out + base + 4) = make_float4(pr[4], pr[5], pr[6], pr[7]);
        *reinterpret_cast<float4*>(mask_out + base)     = make_float4(mk[0], mk[1], mk[2], mk[3]);
        *reinterpret_cast<float4*>(mask_out + base + 4) = make_float4(mk[4], mk[5], mk[6], mk[7]);
    }

    // ---------------- deterministic per-block load reduction -------------
    float (*shred)[E_DIM] = ws;
#pragma unroll
    for (int j = 0; j < 8; j++) shred[ty][tx * 8 + j] = loadacc[j];
    __syncthreads();
    if (tid < E_DIM) {
        float s = 0.f;
#pragma unroll
        for (int t = 0; t < 32; t++) s += shred[t][tid];
        g_partial[(size_t)blockIdx.x * E_DIM + tid] = s;
    }
    __threadfence();

    if (tid == 0)
        s_last = (atomicAdd(&g_counter, 1u) == gridDim.x - 1) ? 1u : 0u;
    __syncthreads();
    if (s_last) {
        const int nblk = (int)gridDim.x;
        const int per = (nblk + 3) >> 2;
        const int e = tid & 63, part = tid >> 6;
        float s = 0.f;
        const int b0 = part * per;
        const int b1 = (b0 + per < nblk) ? b0 + per : nblk;
        for (int b = b0; b < b1; b++)
            s += __ldcg(&g_partial[(size_t)b * E_DIM + e]);
        psum[part][e] = s;
        __syncthreads();
        if (tid < E_DIM) {
            float tot = ((psum[0][tid] + psum[1][tid]) + psum[2][tid]) + psum[3][tid];
            imp[tid] = tot;
            ld[tid]  = tot;
        }
        if (tid == 0) g_counter = 0u;
    }
}

extern "C" void kernel_launch(void* const* d_in, const int* in_sizes, int n_in,
                              void* d_out, int out_size) {
    const float* x    = (const float*)d_in[0];
    const float* W    = (const float*)d_in[1];
    const float* bias = (const float*)d_in[2];
    float* out = (float*)d_out;

    int N = in_sizes[0] / D_DIM;                 // 32768
    float* mask_out = out;
    float* prob_out = out + (size_t)N * E_DIM;
    float* imp      = out + 2 * (size_t)N * E_DIM;
    float* ld       = imp + E_DIM;

    int nblk = N / BR;                           // 128
    router_fused_kernel<<<nblk, NT>>>(x, W, bias, mask_out, prob_out, imp, ld);
}

// round 9
// speedup vs baseline: 1.0039x; 1.0039x over previous
#include <cuda_runtime.h>

#define D_DIM 2048
#define E_DIM 64
#define BR 256
#define DK 32
#define NT 256
#define NTILE (D_DIM / DK)   // 64

__device__ float g_partial[512 * E_DIM];
__device__ unsigned int g_counter = 0;

static __device__ __forceinline__ unsigned long long pack2(float lo, float hi) {
    unsigned long long r;
    asm("mov.b64 %0, {%1, %2};" : "=l"(r) : "f"(lo), "f"(hi));
    return r;
}
static __device__ __forceinline__ void unpack2(unsigned long long v, float& lo, float& hi) {
    asm("mov.b64 {%0, %1}, %2;" : "=f"(lo), "=f"(hi) : "l"(v));
}
static __device__ __forceinline__ void fma2(unsigned long long& d, unsigned long long a, unsigned long long b) {
    asm("fma.rn.f32x2 %0, %1, %2, %0;" : "+l"(d) : "l"(a), "l"(b));
}

__global__ __launch_bounds__(NT, 1) void router_fused_kernel(
    const float* __restrict__ x, const float* __restrict__ W,
    const float* __restrict__ bias,
    float* __restrict__ mask_out, float* __restrict__ prob_out,
    float* __restrict__ imp, float* __restrict__ ld)
{
    // x transposed: xs[k][row], row column XOR-swizzled by 4*((k>>2)&7).
    // -> transpose STS conflict-free, mainloop LDS.128 conflict-free, 16B aligned.
    __shared__ float xs[DK][BR];            // 32 KB
    // W tile chunk-permuted: chunk c16 -> float offset (c16>>1)*4 + (c16&1)*32,
    // so wa/wb LDS.128 chunks hit 8 distinct bank quads.
    __shared__ float ws[DK][E_DIM];         // 8 KB
    __shared__ float psum[4][E_DIM];
    __shared__ unsigned int s_last;

    const int tid = threadIdx.x;
    const int tx = tid & 7;                 // expert group (8 experts)
    const int ty = tid >> 3;                // 0..31 -> rows ty*8..ty*8+7
    const int row0 = blockIdx.x * BR;
    const float* xb = x + (size_t)row0 * D_DIM;

    // accumulators: 8 rows x 4 f32x2 pairs (8 experts), bias folded in
    unsigned long long acc2[8][4];
    {
        float b0[8];
#pragma unroll
        for (int j = 0; j < 8; j++) b0[j] = bias[tx * 8 + j];
#pragma unroll
        for (int i = 0; i < 8; i++)
#pragma unroll
            for (int j = 0; j < 4; j++)
                acc2[i][j] = pack2(b0[2 * j], b0[2 * j + 1]);
    }

    // software pipeline registers
    float4 xr[8], wr[2];
#pragma unroll
    for (int p = 0; p < 8; p++)
        xr[p] = *reinterpret_cast<const float4*>(xb + (size_t)(ty + p * 32) * D_DIM + tx * 4);
#pragma unroll
    for (int q = 0; q < 2; q++) {
        int id = tid * 2 + q;
        wr[q] = *reinterpret_cast<const float4*>(W + (size_t)(id >> 4) * E_DIM + (id & 15) * 4);
    }

    for (int t = 0; t < NTILE; t++) {
        // commit x transposed with swizzle: phys col = r ^ (4*tx), k = tx*4+j
#pragma unroll
        for (int p = 0; p < 8; p++) {
            int r = ty + p * 32;
            int pc = r ^ (tx * 4);
            xs[tx * 4 + 0][pc] = xr[p].x;
            xs[tx * 4 + 1][pc] = xr[p].y;
            xs[tx * 4 + 2][pc] = xr[p].z;
            xs[tx * 4 + 3][pc] = xr[p].w;
        }
#pragma unroll
        for (int q = 0; q < 2; q++) {
            int id = tid * 2 + q;
            int kk = id >> 4, c16 = id & 15;
            int dst = (c16 >> 1) * 4 + (c16 & 1) * 32;
            *reinterpret_cast<float4*>(&ws[kk][dst]) = wr[q];
        }
        __syncthreads();

        // next tile's global loads (hidden behind compute)
        if (t + 1 < NTILE) {
            const int k0 = (t + 1) * DK;
#pragma unroll
            for (int p = 0; p < 8; p++)
                xr[p] = *reinterpret_cast<const float4*>(xb + (size_t)(ty + p * 32) * D_DIM + k0 + tx * 4);
#pragma unroll
            for (int q = 0; q < 2; q++) {
                int id = tid * 2 + q;
                wr[q] = *reinterpret_cast<const float4*>(W + (size_t)(k0 + (id >> 4)) * E_DIM + (id & 15) * 4);
            }
        }

#pragma unroll
        for (int kk = 0; kk < DK; kk++) {
            ulonglong2 wa = *reinterpret_cast<const ulonglong2*>(&ws[kk][tx * 4]);       // e 8tx..+3
            ulonglong2 wb = *reinterpret_cast<const ulonglong2*>(&ws[kk][32 + tx * 4]);  // e 8tx+4..+7
            const int swz = 4 * ((kk >> 2) & 7);
            float4 xa = *reinterpret_cast<const float4*>(&xs[kk][(ty * 8) ^ swz]);       // rows ty*8..+3
            float4 xb4 = *reinterpret_cast<const float4*>(&xs[kk][(ty * 8 + 4) ^ swz]);  // rows ty*8+4..+7
            const float xv[8] = {xa.x, xa.y, xa.z, xa.w, xb4.x, xb4.y, xb4.z, xb4.w};
#pragma unroll
            for (int i = 0; i < 8; i++) {
                unsigned long long xx = pack2(xv[i], xv[i]);
                fma2(acc2[i][0], xx, wa.x);
                fma2(acc2[i][1], xx, wa.y);
                fma2(acc2[i][2], xx, wb.x);
                fma2(acc2[i][3], xx, wb.y);
            }
        }
        __syncthreads();
    }

    // ---------------- epilogue: softmax + top-3 + outputs ----------------
    float loadacc[8];
#pragma unroll
    for (int j = 0; j < 8; j++) loadacc[j] = 0.f;

#pragma unroll
    for (int i = 0; i < 8; i++) {
        float lg[8];
#pragma unroll
        for (int j = 0; j < 4; j++) unpack2(acc2[i][j], lg[2 * j], lg[2 * j + 1]);

        float m = lg[0];
#pragma unroll
        for (int j = 1; j < 8; j++) m = fmaxf(m, lg[j]);
#pragma unroll
        for (int d = 1; d < 8; d <<= 1) m = fmaxf(m, __shfl_xor_sync(0xffffffffu, m, d));
        float ev[8], ssum = 0.f;
#pragma unroll
        for (int j = 0; j < 8; j++) { ev[j] = __expf(lg[j] - m); ssum += ev[j]; }
#pragma unroll
        for (int d = 1; d < 8; d <<= 1) ssum += __shfl_xor_sync(0xffffffffu, ssum, d);
        float inv = 1.0f / ssum;

        unsigned chosenMask = 0u;
#pragma unroll
        for (int t = 0; t < 3; t++) {
            float bvv = -3.0e38f; int bi = 1 << 20;
#pragma unroll
            for (int j = 0; j < 8; j++) {
                float v = ((chosenMask >> j) & 1u) ? -3.0e38f : lg[j];
                if (v > bvv) { bvv = v; bi = tx * 8 + j; }
            }
#pragma unroll
            for (int d = 1; d < 8; d <<= 1) {
                float ov = __shfl_xor_sync(0xffffffffu, bvv, d);
                int   oi = __shfl_xor_sync(0xffffffffu, bi, d);
                if (ov > bvv || (ov == bvv && oi < bi)) { bvv = ov; bi = oi; }
            }
            if ((bi >> 3) == tx) chosenMask |= 1u << (bi & 7);
        }

        float pr[8], mk[8];
#pragma unroll
        for (int j = 0; j < 8; j++) {
            pr[j] = ev[j] * inv;
            mk[j] = ((chosenMask >> j) & 1u) ? 1.0f : 0.0f;
            loadacc[j] += pr[j];
        }
        size_t base = ((size_t)(row0 + ty * 8 + i)) * E_DIM + tx * 8;
        *reinterpret_cast<float4*>(prob_out + base)     = make_float4(pr[0], pr[1], pr[2], pr[3]);
        *reinterpret_cast<float4*>(prob_out + base + 4) = make_float4(pr[4], pr[5], pr[6], pr[7]);
        *reinterpret_cast<float4*>(mask_out + base)     = make_float4(mk[0], mk[1], mk[2], mk[3]);
        *reinterpret_cast<float4*>(mask_out + base + 4) = make_float4(mk[4], mk[5], mk[6], mk[7]);
    }

    // ---------------- deterministic per-block load reduction -------------
    float (*shred)[E_DIM] = ws;
#pragma unroll
    for (int j = 0; j < 8; j++) shred[ty][tx * 8 + j] = loadacc[j];
    __syncthreads();
    if (tid < E_DIM) {
        float s = 0.f;
#pragma unroll
        for (int t = 0; t < 32; t++) s += shred[t][tid];
        g_partial[(size_t)blockIdx.x * E_DIM + tid] = s;
    }
    __threadfence();

    if (tid == 0)
        s_last = (atomicAdd(&g_counter, 1u) == gridDim.x - 1) ? 1u : 0u;
    __syncthreads();
    if (s_last) {
        const int nblk = (int)gridDim.x;
        const int per = (nblk + 3) >> 2;
        const int e = tid & 63, part = tid >> 6;
        float s = 0.f;
        const int b0 = part * per;
        const int b1 = (b0 + per < nblk) ? b0 + per : nblk;
        for (int b = b0; b < b1; b++)
            s += __ldcg(&g_partial[(size_t)b * E_DIM + e]);
        psum[part][e] = s;
        __syncthreads();
        if (tid < E_DIM) {
            float tot = ((psum[0][tid] + psum[1][tid]) + psum[2][tid]) + psum[3][tid];
            imp[tid] = tot;
            ld[tid]  = tot;
        }
        if (tid == 0) g_counter = 0u;
    }
}

extern "C" void kernel_launch(void* const* d_in, const int* in_sizes, int n_in,
                              void* d_out, int out_size) {
    const float* x    = (const float*)d_in[0];
    const float* W    = (const float*)d_in[1];
    const float* bias = (const float*)d_in[2];
    float* out = (float*)d_out;

    int N = in_sizes[0] / D_DIM;                 // 32768
    float* mask_out = out;
    float* prob_out = out + (size_t)N * E_DIM;
    float* imp      = out + 2 * (size_t)N * E_DIM;
    float* ld       = imp + E_DIM;

    int nblk = N / BR;                           // 128
    router_fused_kernel<<<nblk, NT>>>(x, W, bias, mask_out, prob_out, imp, ld);
}

// round 10
// speedup vs baseline: 1.0089x; 1.0050x over previous
#include <cuda_runtime.h>

#define D_DIM 2048
#define E_DIM 64
#define BR 256
#define DK 32
#define NT 256
#define NTILE (D_DIM / DK)   // 64

__device__ float g_partial[512 * E_DIM];
__device__ unsigned int g_counter = 0;

static __device__ __forceinline__ unsigned long long pack2(float lo, float hi) {
    unsigned long long r;
    asm("mov.b64 %0, {%1, %2};" : "=l"(r) : "f"(lo), "f"(hi));
    return r;
}
static __device__ __forceinline__ void unpack2(unsigned long long v, float& lo, float& hi) {
    asm("mov.b64 {%0, %1}, %2;" : "=f"(lo), "=f"(hi) : "l"(v));
}
static __device__ __forceinline__ void fma2(unsigned long long& d, unsigned long long a, unsigned long long b) {
    asm("fma.rn.f32x2 %0, %1, %2, %0;" : "+l"(d) : "l"(a), "l"(b));
}

__global__ __launch_bounds__(NT, 1) void router_fused_kernel(
    const float* __restrict__ x, const float* __restrict__ W,
    const float* __restrict__ bias,
    float* __restrict__ mask_out, float* __restrict__ prob_out,
    float* __restrict__ imp, float* __restrict__ ld)
{
    // x transposed: xs[k][row], row column XOR-swizzled by 4*((k>>2)&7).
    // -> transpose STS conflict-free, mainloop LDS.128 conflict-free, 16B aligned.
    __shared__ float xs[DK][BR];            // 32 KB
    // W tile chunk-permuted: chunk c16 -> float offset (c16>>1)*4 + (c16&1)*32,
    // so wa/wb LDS.128 chunks hit 8 distinct bank quads.
    __shared__ float ws[DK][E_DIM];         // 8 KB
    __shared__ float psum[4][E_DIM];
    __shared__ unsigned int s_last;

    const int tid = threadIdx.x;
    const int tx = tid & 7;                 // expert group (8 experts)
    const int ty = tid >> 3;                // 0..31 -> rows ty*8..ty*8+7
    const int row0 = blockIdx.x * BR;
    const float* xb = x + (size_t)row0 * D_DIM;

    // accumulators: 8 rows x 4 f32x2 pairs (8 experts), bias folded in
    unsigned long long acc2[8][4];
    {
        float b0[8];
#pragma unroll
        for (int j = 0; j < 8; j++) b0[j] = bias[tx * 8 + j];
#pragma unroll
        for (int i = 0; i < 8; i++)
#pragma unroll
            for (int j = 0; j < 4; j++)
                acc2[i][j] = pack2(b0[2 * j], b0[2 * j + 1]);
    }

    // software pipeline registers
    float4 xr[8], wr[2];
#pragma unroll
    for (int p = 0; p < 8; p++)
        xr[p] = *reinterpret_cast<const float4*>(xb + (size_t)(ty + p * 32) * D_DIM + tx * 4);
#pragma unroll
    for (int q = 0; q < 2; q++) {
        int id = tid * 2 + q;
        wr[q] = *reinterpret_cast<const float4*>(W + (size_t)(id >> 4) * E_DIM + (id & 15) * 4);
    }

    for (int t = 0; t < NTILE; t++) {
        // commit x transposed with swizzle: phys col = r ^ (4*tx), k = tx*4+j
#pragma unroll
        for (int p = 0; p < 8; p++) {
            int r = ty + p * 32;
            int pc = r ^ (tx * 4);
            xs[tx * 4 + 0][pc] = xr[p].x;
            xs[tx * 4 + 1][pc] = xr[p].y;
            xs[tx * 4 + 2][pc] = xr[p].z;
            xs[tx * 4 + 3][pc] = xr[p].w;
        }
#pragma unroll
        for (int q = 0; q < 2; q++) {
            int id = tid * 2 + q;
            int kk = id >> 4, c16 = id & 15;
            int dst = (c16 >> 1) * 4 + (c16 & 1) * 32;
            *reinterpret_cast<float4*>(&ws[kk][dst]) = wr[q];
        }
        __syncthreads();

        // next tile's global loads (hidden behind compute)
        if (t + 1 < NTILE) {
            const int k0 = (t + 1) * DK;
#pragma unroll
            for (int p = 0; p < 8; p++)
                xr[p] = *reinterpret_cast<const float4*>(xb + (size_t)(ty + p * 32) * D_DIM + k0 + tx * 4);
#pragma unroll
            for (int q = 0; q < 2; q++) {
                int id = tid * 2 + q;
                wr[q] = *reinterpret_cast<const float4*>(W + (size_t)(k0 + (id >> 4)) * E_DIM + (id & 15) * 4);
            }
        }

#pragma unroll
        for (int kk = 0; kk < DK; kk++) {
            ulonglong2 wa = *reinterpret_cast<const ulonglong2*>(&ws[kk][tx * 4]);       // e 8tx..+3
            ulonglong2 wb = *reinterpret_cast<const ulonglong2*>(&ws[kk][32 + tx * 4]);  // e 8tx+4..+7
            const int swz = 4 * ((kk >> 2) & 7);
            float4 xa = *reinterpret_cast<const float4*>(&xs[kk][(ty * 8) ^ swz]);       // rows ty*8..+3
            float4 xb4 = *reinterpret_cast<const float4*>(&xs[kk][(ty * 8 + 4) ^ swz]);  // rows ty*8+4..+7
            const float xv[8] = {xa.x, xa.y, xa.z, xa.w, xb4.x, xb4.y, xb4.z, xb4.w};
#pragma unroll
            for (int i = 0; i < 8; i++) {
                unsigned long long xx = pack2(xv[i], xv[i]);
                fma2(acc2[i][0], xx, wa.x);
                fma2(acc2[i][1], xx, wa.y);
                fma2(acc2[i][2], xx, wb.x);
                fma2(acc2[i][3], xx, wb.y);
            }
        }
        __syncthreads();
    }

    // ---------------- epilogue: softmax + top-3 + outputs ----------------
    float loadacc[8];
#pragma unroll
    for (int j = 0; j < 8; j++) loadacc[j] = 0.f;

#pragma unroll
    for (int i = 0; i < 8; i++) {
        float lg[8];
#pragma unroll
        for (int j = 0; j < 4; j++) unpack2(acc2[i][j], lg[2 * j], lg[2 * j + 1]);

        float m = lg[0];
#pragma unroll
        for (int j = 1; j < 8; j++) m = fmaxf(m, lg[j]);
#pragma unroll
        for (int d = 1; d < 8; d <<= 1) m = fmaxf(m, __shfl_xor_sync(0xffffffffu, m, d));
        float ev[8], ssum = 0.f;
#pragma unroll
        for (int j = 0; j < 8; j++) { ev[j] = __expf(lg[j] - m); ssum += ev[j]; }
#pragma unroll
        for (int d = 1; d < 8; d <<= 1) ssum += __shfl_xor_sync(0xffffffffu, ssum, d);
        float inv = 1.0f / ssum;

        unsigned chosenMask = 0u;
#pragma unroll
        for (int t = 0; t < 3; t++) {
            float bvv = -3.0e38f; int bi = 1 << 20;
#pragma unroll
            for (int j = 0; j < 8; j++) {
                float v = ((chosenMask >> j) & 1u) ? -3.0e38f : lg[j];
                if (v > bvv) { bvv = v; bi = tx * 8 + j; }
            }
#pragma unroll
            for (int d = 1; d < 8; d <<= 1) {
                float ov = __shfl_xor_sync(0xffffffffu, bvv, d);
                int   oi = __shfl_xor_sync(0xffffffffu, bi, d);
                if (ov > bvv || (ov == bvv && oi < bi)) { bvv = ov; bi = oi; }
            }
            if ((bi >> 3) == tx) chosenMask |= 1u << (bi & 7);
        }

        float pr[8], mk[8];
#pragma unroll
        for (int j = 0; j < 8; j++) {
            pr[j] = ev[j] * inv;
            mk[j] = ((chosenMask >> j) & 1u) ? 1.0f : 0.0f;
            loadacc[j] += pr[j];
        }
        size_t base = ((size_t)(row0 + ty * 8 + i)) * E_DIM + tx * 8;
        *reinterpret_cast<float4*>(prob_out + base)     = make_float4(pr[0], pr[1], pr[2], pr[3]);
        *reinterpret_cast<float4*>(prob_out + base + 4) = make_float4(pr[4], pr[5], pr[6], pr[7]);
        *reinterpret_cast<float4*>(mask_out + base)     = make_float4(mk[0], mk[1], mk[2], mk[3]);
        *reinterpret_cast<float4*>(mask_out + base + 4) = make_float4(mk[4], mk[5], mk[6], mk[7]);
    }

    // ---------------- deterministic per-block load reduction -------------
    float (*shred)[E_DIM] = ws;
#pragma unroll
    for (int j = 0; j < 8; j++) shred[ty][tx * 8 + j] = loadacc[j];
    __syncthreads();
    if (tid < E_DIM) {
        float s = 0.f;
#pragma unroll
        for (int t = 0; t < 32; t++) s += shred[t][tid];
        g_partial[(size_t)blockIdx.x * E_DIM + tid] = s;
    }
    __threadfence();

    if (tid == 0)
        s_last = (atomicAdd(&g_counter, 1u) == gridDim.x - 1) ? 1u : 0u;
    __syncthreads();
    if (s_last) {
        const int nblk = (int)gridDim.x;
        const int per = (nblk + 3) >> 2;
        const int e = tid & 63, part = tid >> 6;
        float s = 0.f;
        const int b0 = part * per;
        const int b1 = (b0 + per < nblk) ? b0 + per : nblk;
        for (int b = b0; b < b1; b++)
            s += __ldcg(&g_partial[(size_t)b * E_DIM + e]);
        psum[part][e] = s;
        __syncthreads();
        if (tid < E_DIM) {
            float tot = ((psum[0][tid] + psum[1][tid]) + psum[2][tid]) + psum[3][tid];
            imp[tid] = tot;
            ld[tid]  = tot;
        }
        if (tid == 0) g_counter = 0u;
    }
}

extern "C" void kernel_launch(void* const* d_in, const int* in_sizes, int n_in,
                              void* d_out, int out_size) {
    const float* x    = (const float*)d_in[0];
    const float* W    = (const float*)d_in[1];
    const float* bias = (const float*)d_in[2];
    float* out = (float*)d_out;

    int N = in_sizes[0] / D_DIM;                 // 32768
    float* mask_out = out;
    float* prob_out = out + (size_t)N * E_DIM;
    float* imp      = out + 2 * (size_t)N * E_DIM;
    float* ld       = imp + E_DIM;

    int nblk = N / BR;                           // 128
    router_fused_kernel<<<nblk, NT>>>(x, W, bias, mask_out, prob_out, imp, ld);
}